// round 4
// baseline (speedup 1.0000x reference)
#include <cuda_runtime.h>

#define MAX_B 1024
#define MEAN_CHUNKS 64
#define MAGS_PER_TF 9

// Per-image per-chunk partial sums. Written by every mean block that does
// work (contrast images only); read only for those same images.
__device__ float g_part[MAX_B * MEAN_CHUNKS];

// ---------------------------------------------------------------------------
// Kernel 1: partial per-image sums, ONLY for images applying contrast.
// Cached loads (NOT streaming): the apply kernel re-reads these same lines,
// and we want them resident in L2.
// ---------------------------------------------------------------------------
__global__ void mean_kernel(const float4* __restrict__ x,
                            const int* __restrict__ sample,
                            const int* __restrict__ apply_mask,
                            int vec_per_img)
{
    const int b     = blockIdx.x;
    const int chunk = blockIdx.y;

    const int s  = __ldg(&sample[b]);
    const int tf = s / MAGS_PER_TF;
    if (!((tf == 1) && (__ldg(&apply_mask[s]) > 0))) return;  // skip the read

    const int chunk_vecs = (vec_per_img + MEAN_CHUNKS - 1) / MEAN_CHUNKS;
    const int start = chunk * chunk_vecs;
    const int end   = min(start + chunk_vecs, vec_per_img);

    const float4* img = x + (size_t)b * vec_per_img;
    float acc = 0.0f;
    for (int i = start + threadIdx.x; i < end; i += blockDim.x) {
        float4 v = __ldg(&img[i]);   // cached: stays in L2 for the apply pass
        acc += (v.x + v.y) + (v.z + v.w);
    }

    #pragma unroll
    for (int off = 16; off > 0; off >>= 1)
        acc += __shfl_xor_sync(0xFFFFFFFFu, acc, off);

    __shared__ float warp_sums[8];
    const int lane = threadIdx.x & 31;
    const int wid  = threadIdx.x >> 5;
    if (lane == 0) warp_sums[wid] = acc;
    __syncthreads();

    if (wid == 0) {
        const int nwarps = (blockDim.x + 31) >> 5;
        float v = (lane < nwarps) ? warp_sums[lane] : 0.0f;
        #pragma unroll
        for (int off = 4; off > 0; off >>= 1)
            v += __shfl_xor_sync(0xFFFFFFFFu, v, off);
        if (lane == 0)
            g_part[b * MEAN_CHUNKS + chunk] = v;
    }
}

// ---------------------------------------------------------------------------
// Kernel 2: out = saturate(alpha[b]*x + beta[b]).
// Exact tiling: 37632 vecs/img = 256 threads * 3 vecs * 49 blocks.
// Flattened 1-D grid, no bounds predicates anywhere.
// ---------------------------------------------------------------------------
#define APPLY_VPT 3
#define APPLY_THREADS 256

__global__ void __launch_bounds__(APPLY_THREADS)
apply_kernel(const float4* __restrict__ x,
             const int* __restrict__ sample,
             const int* __restrict__ apply_mask,
             float4* __restrict__ out,
             int blocks_per_img,
             int vec_per_img)
{
    const int b       = blockIdx.x / blocks_per_img;
    const int blk_in  = blockIdx.x - b * blocks_per_img;

    const int s  = __ldg(&sample[b]);
    const int tf = s / MAGS_PER_TF;
    const float mag = (float)(s % MAGS_PER_TF + 1) * 0.1f;
    const bool applied = (__ldg(&apply_mask[s]) > 0);

    float alpha = 1.0f, beta = 0.0f;
    if (applied) {
        if (tf == 0) {                       // brightness: x + mag
            beta = mag;
        } else if (tf == 1) {                // contrast: (1+mag)x - mag*mean
            float sum = 0.0f;
            #pragma unroll
            for (int c = 0; c < MEAN_CHUNKS; c++)
                sum += __ldg(&g_part[b * MEAN_CHUNKS + c]);
            const float m = sum / (float)(vec_per_img * 4);
            alpha = 1.0f + mag;  beta = -m * mag;
        } else if (tf == 2) {                // invert blend: (1-2mag)x + mag
            alpha = 1.0f - 2.0f * mag; beta = mag;
        } else {                             // gain: (1+mag)x
            alpha = 1.0f + mag;
        }
    }

    const size_t base = (size_t)b * vec_per_img
                      + (size_t)blk_in * (APPLY_THREADS * APPLY_VPT)
                      + threadIdx.x;

    float4 v[APPLY_VPT];
    #pragma unroll
    for (int k = 0; k < APPLY_VPT; k++)
        v[k] = __ldcs(&x[base + k * APPLY_THREADS]);

    #pragma unroll
    for (int k = 0; k < APPLY_VPT; k++) {
        v[k].x = __saturatef(fmaf(alpha, v[k].x, beta));
        v[k].y = __saturatef(fmaf(alpha, v[k].y, beta));
        v[k].z = __saturatef(fmaf(alpha, v[k].z, beta));
        v[k].w = __saturatef(fmaf(alpha, v[k].w, beta));
        __stcs(&out[base + k * APPLY_THREADS], v[k]);
    }
}

// Fallback (general shapes): predicated version, grid.y = batch.
__global__ void __launch_bounds__(APPLY_THREADS)
apply_kernel_generic(const float4* __restrict__ x,
                     const int* __restrict__ sample,
                     const int* __restrict__ apply_mask,
                     float4* __restrict__ out,
                     int vec_per_img)
{
    const int b = blockIdx.y;
    const int i = blockIdx.x * blockDim.x + threadIdx.x;

    const int s  = __ldg(&sample[b]);
    const int tf = s / MAGS_PER_TF;
    const float mag = (float)(s % MAGS_PER_TF + 1) * 0.1f;
    const bool applied = (__ldg(&apply_mask[s]) > 0);

    float alpha = 1.0f, beta = 0.0f;
    if (applied) {
        if (tf == 0) { beta = mag; }
        else if (tf == 1) {
            float sum = 0.0f;
            #pragma unroll
            for (int c = 0; c < MEAN_CHUNKS; c++)
                sum += __ldg(&g_part[b * MEAN_CHUNKS + c]);
            const float m = sum / (float)(vec_per_img * 4);
            alpha = 1.0f + mag;  beta = -m * mag;
        }
        else if (tf == 2) { alpha = 1.0f - 2.0f * mag; beta = mag; }
        else { alpha = 1.0f + mag; }
    }

    if (i < vec_per_img) {
        const size_t idx = (size_t)b * vec_per_img + i;
        float4 v = __ldcs(&x[idx]);
        v.x = __saturatef(fmaf(alpha, v.x, beta));
        v.y = __saturatef(fmaf(alpha, v.y, beta));
        v.z = __saturatef(fmaf(alpha, v.z, beta));
        v.w = __saturatef(fmaf(alpha, v.w, beta));
        __stcs(&out[idx], v);
    }
}

// ---------------------------------------------------------------------------
extern "C" void kernel_launch(void* const* d_in, const int* in_sizes, int n_in,
                              void* d_out, int out_size)
{
    const float* x          = (const float*)d_in[0];
    const int*   sample     = (const int*)d_in[1];
    const int*   apply_mask = (const int*)d_in[2];
    float*       out        = (float*)d_out;

    const int B = in_sizes[1];                 // 256
    const int elems_per_img = in_sizes[0] / B; // 150528
    const int vec_per_img = elems_per_img / 4; // 37632

    // Pass 1: conditional per-image partial sums
    dim3 mgrid(B, MEAN_CHUNKS);
    mean_kernel<<<mgrid, 256>>>((const float4*)x, sample, apply_mask, vec_per_img);

    // Pass 2: streaming affine+clamp
    const int tile = APPLY_THREADS * APPLY_VPT;   // 768
    if (vec_per_img % tile == 0) {
        const int blocks_per_img = vec_per_img / tile;   // 49
        apply_kernel<<<B * blocks_per_img, APPLY_THREADS>>>(
            (const float4*)x, sample, apply_mask, (float4*)out,
            blocks_per_img, vec_per_img);
    } else {
        dim3 grid((vec_per_img + APPLY_THREADS - 1) / APPLY_THREADS, B);
        apply_kernel_generic<<<grid, APPLY_THREADS>>>(
            (const float4*)x, sample, apply_mask, (float4*)out, vec_per_img);
    }
}

// round 5
// speedup vs baseline: 1.1435x; 1.1435x over previous
#include <cuda_runtime.h>

#define MAX_B        1024
#define MAGS_PER_TF  9
#define THREADS      192
#define VPT          4
#define NWARPS       (THREADS / 32)

// Persistent device state. Zero-initialized at module load.
// g_done : monotonic per-image block-completion counter (counts across replays)
// g_sum  : per-image running sum for the CURRENT epoch (reset via atomicExch)
// g_flag : monotonic per-image epoch flag (last block publishes epoch number)
// g_mean : published mean for the current epoch
__device__ unsigned int          g_done[MAX_B];
__device__ float                 g_sum[MAX_B];
__device__ volatile unsigned int g_flag[MAX_B];
__device__ volatile float        g_mean[MAX_B];

// For the generic (non-exact-tiling) fallback path:
#define MEAN_CHUNKS 32
__device__ float g_part[MAX_B * MEAN_CHUNKS];

// ---------------------------------------------------------------------------
__device__ __forceinline__ float block_reduce(float val)
{
    #pragma unroll
    for (int off = 16; off > 0; off >>= 1)
        val += __shfl_xor_sync(0xFFFFFFFFu, val, off);

    __shared__ float ws[8];
    const int lane = threadIdx.x & 31;
    const int wid  = threadIdx.x >> 5;
    if (lane == 0) ws[wid] = val;
    __syncthreads();

    float v = 0.0f;
    if (wid == 0) {
        v = (lane < NWARPS) ? ws[lane] : 0.0f;
        #pragma unroll
        for (int off = 4; off > 0; off >>= 1)
            v += __shfl_xor_sync(0xFFFFFFFFu, v, off);
    }
    return v;  // valid in warp 0
}

// ---------------------------------------------------------------------------
// Fused single-pass kernel. Exact tiling: vec_per_img = THREADS*VPT*blocks_per_img.
// ---------------------------------------------------------------------------
__global__ void __launch_bounds__(THREADS)
fused_kernel(const float4* __restrict__ x,
             const int* __restrict__ sample,
             const int* __restrict__ apply_mask,
             float4* __restrict__ out,
             int blocks_per_img,
             int vec_per_img)
{
    const int b   = blockIdx.x / blocks_per_img;
    const int blk = blockIdx.x - b * blocks_per_img;

    const int s  = __ldg(&sample[b]);
    const int tf = s / MAGS_PER_TF;
    const float mag = (float)(s % MAGS_PER_TF + 1) * 0.1f;
    const bool applied  = (__ldg(&apply_mask[s]) > 0);
    const bool contrast = applied && (tf == 1);

    const size_t base = (size_t)b * vec_per_img
                      + (size_t)blk * (THREADS * VPT)
                      + threadIdx.x;

    // Front-batched streaming loads (MLP=4)
    float4 v[VPT];
    #pragma unroll
    for (int k = 0; k < VPT; k++)
        v[k] = __ldcs(&x[base + k * THREADS]);

    float alpha = 1.0f, beta = 0.0f;
    if (applied) {
        if (tf == 0)      { beta = mag; }                        // brightness
        else if (tf == 2) { alpha = 1.0f - 2.0f * mag; beta = mag; }  // invert
        else if (tf == 3) { alpha = 1.0f + mag; }                // gain
        // tf == 1 (contrast) handled below after the mean is known
    }

    if (contrast) {
        // Block-local partial sum from data already in registers.
        float acc = 0.0f;
        #pragma unroll
        for (int k = 0; k < VPT; k++)
            acc += (v[k].x + v[k].y) + (v[k].z + v[k].w);
        float total = block_reduce(acc);

        __shared__ float s_mean;
        __shared__ int   s_fallback;
        const float inv_n = 1.0f / (float)(vec_per_img * 4);

        if (threadIdx.x == 0) {
            s_fallback = 0;
            atomicAdd(&g_sum[b], total);
            __threadfence();   // sum visible before the done-count increment
            const unsigned int d = atomicAdd(&g_done[b], 1u) + 1u;
            const unsigned int bp = (unsigned int)blocks_per_img;
            const unsigned int my_epoch = (d + bp - 1u) / bp;

            if (d % bp == 0u) {
                // Last block of this image for this epoch: all sums landed.
                float sum = atomicExch(&g_sum[b], 0.0f);  // read + reset
                float m = sum * inv_n;
                g_mean[b] = m;
                __threadfence();
                g_flag[b] = my_epoch;   // publish (monotonic)
                s_mean = m;
            } else {
                // Bounded spin on the epoch flag.
                int spins = 0;
                bool ok = true;
                while (g_flag[b] < my_epoch) {
                    __nanosleep(40);
                    if (++spins > 2000000) { ok = false; break; }
                }
                if (ok) {
                    __threadfence();    // acquire
                    s_mean = g_mean[b];
                } else {
                    s_fallback = 1;     // provable forward progress
                }
            }
        }
        __syncthreads();

        if (s_fallback) {
            // Never expected in practice: recompute the full image mean locally.
            const float4* img = x + (size_t)b * vec_per_img;
            float a2 = 0.0f;
            for (int i = threadIdx.x; i < vec_per_img; i += THREADS) {
                float4 w = __ldg(&img[i]);
                a2 += (w.x + w.y) + (w.z + w.w);
            }
            __syncthreads();  // reuse of ws[] in block_reduce
            float t2 = block_reduce(a2);
            if (threadIdx.x == 0) s_mean = t2 * inv_n;
            __syncthreads();
        }

        alpha = 1.0f + mag;
        beta  = -s_mean * mag;
    }

    #pragma unroll
    for (int k = 0; k < VPT; k++) {
        v[k].x = __saturatef(fmaf(alpha, v[k].x, beta));
        v[k].y = __saturatef(fmaf(alpha, v[k].y, beta));
        v[k].z = __saturatef(fmaf(alpha, v[k].z, beta));
        v[k].w = __saturatef(fmaf(alpha, v[k].w, beta));
        __stcs(&out[base + k * THREADS], v[k]);
    }
}

// ---------------------------------------------------------------------------
// Generic fallback path (shapes without exact tiling): two-kernel scheme.
// ---------------------------------------------------------------------------
__global__ void mean_kernel(const float4* __restrict__ x,
                            const int* __restrict__ sample,
                            const int* __restrict__ apply_mask,
                            int vec_per_img)
{
    const int b     = blockIdx.x;
    const int chunk = blockIdx.y;

    const int s  = __ldg(&sample[b]);
    const int tf = s / MAGS_PER_TF;
    if (!((tf == 1) && (__ldg(&apply_mask[s]) > 0))) return;

    const int chunk_vecs = (vec_per_img + MEAN_CHUNKS - 1) / MEAN_CHUNKS;
    const int start = chunk * chunk_vecs;
    const int end   = min(start + chunk_vecs, vec_per_img);

    const float4* img = x + (size_t)b * vec_per_img;
    float acc = 0.0f;
    for (int i = start + threadIdx.x; i < end; i += blockDim.x) {
        float4 w = __ldg(&img[i]);
        acc += (w.x + w.y) + (w.z + w.w);
    }
    #pragma unroll
    for (int off = 16; off > 0; off >>= 1)
        acc += __shfl_xor_sync(0xFFFFFFFFu, acc, off);

    __shared__ float ws[32];
    const int lane = threadIdx.x & 31;
    const int wid  = threadIdx.x >> 5;
    if (lane == 0) ws[wid] = acc;
    __syncthreads();
    if (wid == 0) {
        const int nwarps = (blockDim.x + 31) >> 5;
        float t = (lane < nwarps) ? ws[lane] : 0.0f;
        #pragma unroll
        for (int off = 16; off > 0; off >>= 1)
            t += __shfl_xor_sync(0xFFFFFFFFu, t, off);
        if (lane == 0) g_part[b * MEAN_CHUNKS + chunk] = t;
    }
}

__global__ void apply_generic(const float4* __restrict__ x,
                              const int* __restrict__ sample,
                              const int* __restrict__ apply_mask,
                              float4* __restrict__ out,
                              int vec_per_img)
{
    const int b = blockIdx.y;
    const int i = blockIdx.x * blockDim.x + threadIdx.x;

    const int s  = __ldg(&sample[b]);
    const int tf = s / MAGS_PER_TF;
    const float mag = (float)(s % MAGS_PER_TF + 1) * 0.1f;
    const bool applied = (__ldg(&apply_mask[s]) > 0);

    float alpha = 1.0f, beta = 0.0f;
    if (applied) {
        if (tf == 0) { beta = mag; }
        else if (tf == 1) {
            float sum = 0.0f;
            #pragma unroll
            for (int c = 0; c < MEAN_CHUNKS; c++)
                sum += __ldg(&g_part[b * MEAN_CHUNKS + c]);
            alpha = 1.0f + mag;
            beta  = -(sum / (float)(vec_per_img * 4)) * mag;
        }
        else if (tf == 2) { alpha = 1.0f - 2.0f * mag; beta = mag; }
        else              { alpha = 1.0f + mag; }
    }

    if (i < vec_per_img) {
        const size_t idx = (size_t)b * vec_per_img + i;
        float4 w = __ldcs(&x[idx]);
        w.x = __saturatef(fmaf(alpha, w.x, beta));
        w.y = __saturatef(fmaf(alpha, w.y, beta));
        w.z = __saturatef(fmaf(alpha, w.z, beta));
        w.w = __saturatef(fmaf(alpha, w.w, beta));
        __stcs(&out[idx], w);
    }
}

// ---------------------------------------------------------------------------
extern "C" void kernel_launch(void* const* d_in, const int* in_sizes, int n_in,
                              void* d_out, int out_size)
{
    const float* x          = (const float*)d_in[0];
    const int*   sample     = (const int*)d_in[1];
    const int*   apply_mask = (const int*)d_in[2];
    float*       out        = (float*)d_out;

    const int B = in_sizes[1];                 // 256
    const int elems_per_img = in_sizes[0] / B; // 150528
    const int vec_per_img = elems_per_img / 4; // 37632

    const int tile = THREADS * VPT;            // 768
    if ((elems_per_img % 4 == 0) && (vec_per_img % tile == 0) && B <= MAX_B) {
        const int blocks_per_img = vec_per_img / tile;  // 49
        fused_kernel<<<B * blocks_per_img, THREADS>>>(
            (const float4*)x, sample, apply_mask, (float4*)out,
            blocks_per_img, vec_per_img);
    } else {
        dim3 mgrid(B, MEAN_CHUNKS);
        mean_kernel<<<mgrid, 256>>>((const float4*)x, sample, apply_mask, vec_per_img);
        dim3 grid((vec_per_img + 255) / 256, B);
        apply_generic<<<grid, 256>>>((const float4*)x, sample, apply_mask,
                                     (float4*)out, vec_per_img);
    }
}

// round 6
// speedup vs baseline: 1.1585x; 1.0131x over previous
#include <cuda_runtime.h>

#define MAX_B        1024
#define MAGS_PER_TF  9
#define THREADS      192
#define VPT          4
#define NWARPS       (THREADS / 32)

// Persistent device state, zero-initialized at module load. All counters are
// monotonic across graph replays (no reset kernel needed).
__device__ unsigned int          g_done[MAX_B];   // per-image block completions
__device__ float                 g_sum[MAX_B];    // running sum, reset via atomicExch
__device__ volatile unsigned int g_flag[MAX_B];   // published epoch number
__device__ volatile float        g_mean[MAX_B];   // published mean

// Generic (non-exact-tiling) fallback path scratch:
#define MEAN_CHUNKS 32
__device__ float g_part[MAX_B * MEAN_CHUNKS];

// ---------------------------------------------------------------------------
__device__ __forceinline__ float block_reduce(float val)
{
    #pragma unroll
    for (int off = 16; off > 0; off >>= 1)
        val += __shfl_xor_sync(0xFFFFFFFFu, val, off);

    __shared__ float ws[NWARPS];
    const int lane = threadIdx.x & 31;
    const int wid  = threadIdx.x >> 5;
    if (lane == 0) ws[wid] = val;
    __syncthreads();

    float v = 0.0f;
    if (wid == 0) {
        v = (lane < NWARPS) ? ws[lane] : 0.0f;
        #pragma unroll
        for (int off = 4; off > 0; off >>= 1)
            v += __shfl_xor_sync(0xFFFFFFFFu, v, off);
    }
    return v;  // valid in warp 0
}

// ---------------------------------------------------------------------------
// Fused single-pass kernel. Exact tiling: vec_per_img = THREADS*VPT*blocks_per_img.
// Two block-uniform paths keep the common path's register set slim.
// ---------------------------------------------------------------------------
__global__ void __launch_bounds__(THREADS)
fused_kernel(const float4* __restrict__ x,
             const int* __restrict__ sample,
             const int* __restrict__ apply_mask,
             float4* __restrict__ out,
             int blocks_per_img,
             int vec_per_img)
{
    const int b   = blockIdx.x / blocks_per_img;
    const int blk = blockIdx.x - b * blocks_per_img;

    const int s  = __ldg(&sample[b]);
    const int tf = s / MAGS_PER_TF;
    const float mag = (float)(s % MAGS_PER_TF + 1) * 0.1f;
    const bool applied  = (__ldg(&apply_mask[s]) > 0);
    const bool contrast = applied && (tf == 1);

    // 32-bit offsets: total float4 count < 2^31.
    const unsigned int base = (unsigned int)b * (unsigned int)vec_per_img
                            + (unsigned int)blk * (THREADS * VPT)
                            + threadIdx.x;

    if (!contrast) {
        // ---------- slim streaming path (7/8 of blocks) ----------
        float alpha = 1.0f, beta = 0.0f;
        if (applied) {
            if (tf == 0)      { beta = mag; }                          // brightness
            else if (tf == 2) { alpha = 1.0f - 2.0f * mag; beta = mag; } // invert
            else              { alpha = 1.0f + mag; }                  // gain
        }

        float4 v[VPT];
        #pragma unroll
        for (int k = 0; k < VPT; k++)
            v[k] = __ldcs(&x[base + k * THREADS]);

        #pragma unroll
        for (int k = 0; k < VPT; k++) {
            v[k].x = __saturatef(fmaf(alpha, v[k].x, beta));
            v[k].y = __saturatef(fmaf(alpha, v[k].y, beta));
            v[k].z = __saturatef(fmaf(alpha, v[k].z, beta));
            v[k].w = __saturatef(fmaf(alpha, v[k].w, beta));
            __stcs(&out[base + k * THREADS], v[k]);
        }
        return;
    }

    // ---------- contrast path (~1/8 of blocks) ----------
    // Pass 1: sum with CACHING loads so the tile stays L1/L2-resident for the
    // reload below. Temps die before the spin — nothing heavy stays live.
    float acc = 0.0f;
    #pragma unroll
    for (int k = 0; k < VPT; k++) {
        float4 t = __ldg(&x[base + k * THREADS]);
        acc += (t.x + t.y) + (t.z + t.w);
    }
    float total = block_reduce(acc);

    __shared__ float s_mean;
    __shared__ int   s_fallback;
    const float inv_n = 1.0f / (float)(vec_per_img * 4);

    if (threadIdx.x == 0) {
        s_fallback = 0;
        atomicAdd(&g_sum[b], total);
        __threadfence();   // sum visible before the done-count increment
        const unsigned int d  = atomicAdd(&g_done[b], 1u) + 1u;
        const unsigned int bp = (unsigned int)blocks_per_img;
        const unsigned int my_epoch = (d + bp - 1u) / bp;

        if (d % bp == 0u) {
            // Last block of this image for this epoch: all sums landed.
            float sum = atomicExch(&g_sum[b], 0.0f);   // read + reset
            float m = sum * inv_n;
            g_mean[b] = m;
            __threadfence();
            g_flag[b] = my_epoch;                      // publish (monotonic)
            s_mean = m;
        } else {
            int spins = 0;
            while (g_flag[b] < my_epoch) {
                __nanosleep(40);
                if (++spins > 4000000) { s_fallback = 1; break; }
            }
            if (!s_fallback) {
                __threadfence();                        // acquire
                s_mean = g_mean[b];
            }
        }
    }
    __syncthreads();

    if (s_fallback) {
        // Guaranteed forward progress (never expected): recompute locally.
        const float4* img = x + (size_t)b * vec_per_img;
        float a2 = 0.0f;
        for (int i = threadIdx.x; i < vec_per_img; i += THREADS) {
            float4 w = __ldg(&img[i]);
            a2 += (w.x + w.y) + (w.z + w.w);
        }
        __syncthreads();
        float t2 = block_reduce(a2);
        if (threadIdx.x == 0) s_mean = t2 * inv_n;
        __syncthreads();
    }

    const float alpha = 1.0f + mag;
    const float beta  = -s_mean * mag;

    // Pass 2: reload (L1-hot) and write out.
    #pragma unroll
    for (int k = 0; k < VPT; k++) {
        float4 v = __ldg(&x[base + k * THREADS]);
        v.x = __saturatef(fmaf(alpha, v.x, beta));
        v.y = __saturatef(fmaf(alpha, v.y, beta));
        v.z = __saturatef(fmaf(alpha, v.z, beta));
        v.w = __saturatef(fmaf(alpha, v.w, beta));
        __stcs(&out[base + k * THREADS], v);
    }
}

// ---------------------------------------------------------------------------
// Generic fallback path (shapes without exact tiling): two-kernel scheme.
// ---------------------------------------------------------------------------
__global__ void mean_kernel(const float4* __restrict__ x,
                            const int* __restrict__ sample,
                            const int* __restrict__ apply_mask,
                            int vec_per_img)
{
    const int b     = blockIdx.x;
    const int chunk = blockIdx.y;

    const int s  = __ldg(&sample[b]);
    const int tf = s / MAGS_PER_TF;
    if (!((tf == 1) && (__ldg(&apply_mask[s]) > 0))) return;

    const int chunk_vecs = (vec_per_img + MEAN_CHUNKS - 1) / MEAN_CHUNKS;
    const int start = chunk * chunk_vecs;
    const int end   = min(start + chunk_vecs, vec_per_img);

    const float4* img = x + (size_t)b * vec_per_img;
    float acc = 0.0f;
    for (int i = start + threadIdx.x; i < end; i += blockDim.x) {
        float4 w = __ldg(&img[i]);
        acc += (w.x + w.y) + (w.z + w.w);
    }
    #pragma unroll
    for (int off = 16; off > 0; off >>= 1)
        acc += __shfl_xor_sync(0xFFFFFFFFu, acc, off);

    __shared__ float ws[32];
    const int lane = threadIdx.x & 31;
    const int wid  = threadIdx.x >> 5;
    if (lane == 0) ws[wid] = acc;
    __syncthreads();
    if (wid == 0) {
        const int nwarps = (blockDim.x + 31) >> 5;
        float t = (lane < nwarps) ? ws[lane] : 0.0f;
        #pragma unroll
        for (int off = 16; off > 0; off >>= 1)
            t += __shfl_xor_sync(0xFFFFFFFFu, t, off);
        if (lane == 0) g_part[b * MEAN_CHUNKS + chunk] = t;
    }
}

__global__ void apply_generic(const float4* __restrict__ x,
                              const int* __restrict__ sample,
                              const int* __restrict__ apply_mask,
                              float4* __restrict__ out,
                              int vec_per_img)
{
    const int b = blockIdx.y;
    const int i = blockIdx.x * blockDim.x + threadIdx.x;

    const int s  = __ldg(&sample[b]);
    const int tf = s / MAGS_PER_TF;
    const float mag = (float)(s % MAGS_PER_TF + 1) * 0.1f;
    const bool applied = (__ldg(&apply_mask[s]) > 0);

    float alpha = 1.0f, beta = 0.0f;
    if (applied) {
        if (tf == 0) { beta = mag; }
        else if (tf == 1) {
            float sum = 0.0f;
            #pragma unroll
            for (int c = 0; c < MEAN_CHUNKS; c++)
                sum += __ldg(&g_part[b * MEAN_CHUNKS + c]);
            alpha = 1.0f + mag;
            beta  = -(sum / (float)(vec_per_img * 4)) * mag;
        }
        else if (tf == 2) { alpha = 1.0f - 2.0f * mag; beta = mag; }
        else              { alpha = 1.0f + mag; }
    }

    if (i < vec_per_img) {
        const size_t idx = (size_t)b * vec_per_img + i;
        float4 w = __ldcs(&x[idx]);
        w.x = __saturatef(fmaf(alpha, w.x, beta));
        w.y = __saturatef(fmaf(alpha, w.y, beta));
        w.z = __saturatef(fmaf(alpha, w.z, beta));
        w.w = __saturatef(fmaf(alpha, w.w, beta));
        __stcs(&out[idx], w);
    }
}

// ---------------------------------------------------------------------------
extern "C" void kernel_launch(void* const* d_in, const int* in_sizes, int n_in,
                              void* d_out, int out_size)
{
    const float* x          = (const float*)d_in[0];
    const int*   sample     = (const int*)d_in[1];
    const int*   apply_mask = (const int*)d_in[2];
    float*       out        = (float*)d_out;

    const int B = in_sizes[1];                 // 256
    const int elems_per_img = in_sizes[0] / B; // 150528
    const int vec_per_img = elems_per_img / 4; // 37632

    const int tile = THREADS * VPT;            // 768
    if ((elems_per_img % 4 == 0) && (vec_per_img % tile == 0) && B <= MAX_B) {
        const int blocks_per_img = vec_per_img / tile;  // 49
        fused_kernel<<<B * blocks_per_img, THREADS>>>(
            (const float4*)x, sample, apply_mask, (float4*)out,
            blocks_per_img, vec_per_img);
    } else {
        dim3 mgrid(B, MEAN_CHUNKS);
        mean_kernel<<<mgrid, 256>>>((const float4*)x, sample, apply_mask, vec_per_img);
        dim3 grid((vec_per_img + 255) / 256, B);
        apply_generic<<<grid, 256>>>((const float4*)x, sample, apply_mask,
                                     (float4*)out, vec_per_img);
    }
}

// round 7
// speedup vs baseline: 1.1965x; 1.0329x over previous
#include <cuda_runtime.h>

#define MAX_B        1024
#define MAGS_PER_TF  9
#define THREADS      192
#define VPT          4
#define NWARPS       (THREADS / 32)
#define MEAN_CHUNKS_F 16     // front reducer blocks per image (fused path)

// Persistent device state, zero-initialized at module load. All counters are
// monotonic across graph replays — no reset kernel is ever needed.
__device__ unsigned int          g_mdone[MAX_B];  // reducer-block completions
__device__ unsigned int          g_acnt[MAX_B];   // apply-block epoch counter
__device__ float                 g_sum[MAX_B];    // running sum (reset via atomicExch)
__device__ volatile unsigned int g_flag[MAX_B];   // published epoch number
__device__ volatile float        g_mean[MAX_B];   // published mean

// Generic (non-exact-tiling) fallback path scratch:
#define MEAN_CHUNKS_G 32
__device__ float g_part[MAX_B * MEAN_CHUNKS_G];

// ---------------------------------------------------------------------------
__device__ __forceinline__ float block_reduce(float val)
{
    #pragma unroll
    for (int off = 16; off > 0; off >>= 1)
        val += __shfl_xor_sync(0xFFFFFFFFu, val, off);

    __shared__ float ws[NWARPS];
    const int lane = threadIdx.x & 31;
    const int wid  = threadIdx.x >> 5;
    if (lane == 0) ws[wid] = val;
    __syncthreads();

    float v = 0.0f;
    if (wid == 0) {
        v = (lane < NWARPS) ? ws[lane] : 0.0f;
        #pragma unroll
        for (int off = 4; off > 0; off >>= 1)
            v += __shfl_xor_sync(0xFFFFFFFFu, v, off);
    }
    return v;  // valid in warp 0
}

// ---------------------------------------------------------------------------
// Fused kernel. Grid layout:
//   [0, B*MEAN_CHUNKS_F)           front reducer blocks (contrast images only)
//   [B*MEAN_CHUNKS_F, +B*bpi)      apply blocks, 49 per image
// Front blocks are scheduled first (in-order CTA placement), so apply blocks
// for contrast images normally find the mean already published.
// ---------------------------------------------------------------------------
__global__ void __launch_bounds__(THREADS)
fused_kernel(const float4* __restrict__ x,
             const int* __restrict__ sample,
             const int* __restrict__ apply_mask,
             float4* __restrict__ out,
             int blocks_per_img,
             int vec_per_img,
             int B)
{
    const int front = B * MEAN_CHUNKS_F;
    const float inv_n = 1.0f / (float)(vec_per_img * 4);

    if (blockIdx.x < front) {
        // ================= front reducer block =================
        const int b     = blockIdx.x / MEAN_CHUNKS_F;
        const int chunk = blockIdx.x - b * MEAN_CHUNKS_F;

        const int s  = __ldg(&sample[b]);
        const int tf = s / MAGS_PER_TF;
        if (!((tf == 1) && (__ldg(&apply_mask[s]) > 0))) return;  // no read

        const int chunk_vecs = vec_per_img / MEAN_CHUNKS_F;   // exact by launch check
        const unsigned int start = (unsigned int)b * vec_per_img + chunk * chunk_vecs;

        float acc = 0.0f;
        for (int i = threadIdx.x; i < chunk_vecs; i += THREADS) {
            float4 w = __ldg(&x[start + i]);   // cached: apply pass re-reads from L2
            acc += (w.x + w.y) + (w.z + w.w);
        }
        float total = block_reduce(acc);

        if (threadIdx.x == 0) {
            atomicAdd(&g_sum[b], total);
            __threadfence();
            const unsigned int d = atomicAdd(&g_mdone[b], 1u) + 1u;
            if (d % (unsigned int)MEAN_CHUNKS_F == 0u) {
                // Last reducer for this image this epoch.
                float sum = atomicExch(&g_sum[b], 0.0f);
                g_mean[b] = sum * inv_n;
                __threadfence();
                g_flag[b] = d / (unsigned int)MEAN_CHUNKS_F;  // publish epoch
            }
        }
        return;
    }

    // ================= apply block =================
    const int abix = blockIdx.x - front;
    const int b    = abix / blocks_per_img;
    const int blk  = abix - b * blocks_per_img;

    const int s  = __ldg(&sample[b]);
    const int tf = s / MAGS_PER_TF;
    const float mag = (float)(s % MAGS_PER_TF + 1) * 0.1f;
    const bool applied  = (__ldg(&apply_mask[s]) > 0);
    const bool contrast = applied && (tf == 1);

    const unsigned int base = (unsigned int)b * (unsigned int)vec_per_img
                            + (unsigned int)blk * (THREADS * VPT)
                            + threadIdx.x;

    if (!contrast) {
        // ---------- slim streaming path (7/8 of blocks) ----------
        float alpha = 1.0f, beta = 0.0f;
        if (applied) {
            if (tf == 0)      { beta = mag; }                            // brightness
            else if (tf == 2) { alpha = 1.0f - 2.0f * mag; beta = mag; } // invert
            else              { alpha = 1.0f + mag; }                    // gain
        }

        float4 v[VPT];
        #pragma unroll
        for (int k = 0; k < VPT; k++)
            v[k] = __ldcs(&x[base + k * THREADS]);

        #pragma unroll
        for (int k = 0; k < VPT; k++) {
            v[k].x = __saturatef(fmaf(alpha, v[k].x, beta));
            v[k].y = __saturatef(fmaf(alpha, v[k].y, beta));
            v[k].z = __saturatef(fmaf(alpha, v[k].z, beta));
            v[k].w = __saturatef(fmaf(alpha, v[k].w, beta));
            __stcs(&out[base + k * THREADS], v[k]);
        }
        return;
    }

    // ---------- contrast path: mean normally already published ----------
    __shared__ float s_mean;
    __shared__ int   s_fallback;

    if (threadIdx.x == 0) {
        s_fallback = 0;
        const unsigned int d = atomicAdd(&g_acnt[b], 1u) + 1u;
        const unsigned int bp = (unsigned int)blocks_per_img;
        const unsigned int my_epoch = (d + bp - 1u) / bp;

        int spins = 0;
        while (g_flag[b] < my_epoch) {          // expected: already satisfied
            __nanosleep(40);
            if (++spins > 4000000) { s_fallback = 1; break; }
        }
        if (!s_fallback) {
            __threadfence();                     // acquire
            s_mean = g_mean[b];
        }
    }
    __syncthreads();

    if (s_fallback) {
        // Guaranteed forward progress (never expected): recompute locally.
        const float4* img = x + (size_t)b * vec_per_img;
        float a2 = 0.0f;
        for (int i = threadIdx.x; i < vec_per_img; i += THREADS) {
            float4 w = __ldg(&img[i]);
            a2 += (w.x + w.y) + (w.z + w.w);
        }
        __syncthreads();
        float t2 = block_reduce(a2);
        if (threadIdx.x == 0) s_mean = t2 * inv_n;
        __syncthreads();
    }

    const float alpha = 1.0f + mag;
    const float beta  = -s_mean * mag;

    // Single pass: data is L2-warm from the reducer blocks.
    float4 v[VPT];
    #pragma unroll
    for (int k = 0; k < VPT; k++)
        v[k] = __ldg(&x[base + k * THREADS]);

    #pragma unroll
    for (int k = 0; k < VPT; k++) {
        v[k].x = __saturatef(fmaf(alpha, v[k].x, beta));
        v[k].y = __saturatef(fmaf(alpha, v[k].y, beta));
        v[k].z = __saturatef(fmaf(alpha, v[k].z, beta));
        v[k].w = __saturatef(fmaf(alpha, v[k].w, beta));
        __stcs(&out[base + k * THREADS], v[k]);
    }
}

// ---------------------------------------------------------------------------
// Generic fallback (shapes without exact tiling): two-kernel scheme.
// ---------------------------------------------------------------------------
__global__ void mean_kernel(const float4* __restrict__ x,
                            const int* __restrict__ sample,
                            const int* __restrict__ apply_mask,
                            int vec_per_img)
{
    const int b     = blockIdx.x;
    const int chunk = blockIdx.y;

    const int s  = __ldg(&sample[b]);
    const int tf = s / MAGS_PER_TF;
    if (!((tf == 1) && (__ldg(&apply_mask[s]) > 0))) return;

    const int chunk_vecs = (vec_per_img + MEAN_CHUNKS_G - 1) / MEAN_CHUNKS_G;
    const int start = chunk * chunk_vecs;
    const int end   = min(start + chunk_vecs, vec_per_img);

    const float4* img = x + (size_t)b * vec_per_img;
    float acc = 0.0f;
    for (int i = start + threadIdx.x; i < end; i += blockDim.x) {
        float4 w = __ldg(&img[i]);
        acc += (w.x + w.y) + (w.z + w.w);
    }
    #pragma unroll
    for (int off = 16; off > 0; off >>= 1)
        acc += __shfl_xor_sync(0xFFFFFFFFu, acc, off);

    __shared__ float ws[32];
    const int lane = threadIdx.x & 31;
    const int wid  = threadIdx.x >> 5;
    if (lane == 0) ws[wid] = acc;
    __syncthreads();
    if (wid == 0) {
        const int nwarps = (blockDim.x + 31) >> 5;
        float t = (lane < nwarps) ? ws[lane] : 0.0f;
        #pragma unroll
        for (int off = 16; off > 0; off >>= 1)
            t += __shfl_xor_sync(0xFFFFFFFFu, t, off);
        if (lane == 0) g_part[b * MEAN_CHUNKS_G + chunk] = t;
    }
}

__global__ void apply_generic(const float4* __restrict__ x,
                              const int* __restrict__ sample,
                              const int* __restrict__ apply_mask,
                              float4* __restrict__ out,
                              int vec_per_img)
{
    const int b = blockIdx.y;
    const int i = blockIdx.x * blockDim.x + threadIdx.x;

    const int s  = __ldg(&sample[b]);
    const int tf = s / MAGS_PER_TF;
    const float mag = (float)(s % MAGS_PER_TF + 1) * 0.1f;
    const bool applied = (__ldg(&apply_mask[s]) > 0);

    float alpha = 1.0f, beta = 0.0f;
    if (applied) {
        if (tf == 0) { beta = mag; }
        else if (tf == 1) {
            float sum = 0.0f;
            #pragma unroll
            for (int c = 0; c < MEAN_CHUNKS_G; c++)
                sum += __ldg(&g_part[b * MEAN_CHUNKS_G + c]);
            alpha = 1.0f + mag;
            beta  = -(sum / (float)(vec_per_img * 4)) * mag;
        }
        else if (tf == 2) { alpha = 1.0f - 2.0f * mag; beta = mag; }
        else              { alpha = 1.0f + mag; }
    }

    if (i < vec_per_img) {
        const size_t idx = (size_t)b * vec_per_img + i;
        float4 w = __ldcs(&x[idx]);
        w.x = __saturatef(fmaf(alpha, w.x, beta));
        w.y = __saturatef(fmaf(alpha, w.y, beta));
        w.z = __saturatef(fmaf(alpha, w.z, beta));
        w.w = __saturatef(fmaf(alpha, w.w, beta));
        __stcs(&out[idx], w);
    }
}

// ---------------------------------------------------------------------------
extern "C" void kernel_launch(void* const* d_in, const int* in_sizes, int n_in,
                              void* d_out, int out_size)
{
    const float* x          = (const float*)d_in[0];
    const int*   sample     = (const int*)d_in[1];
    const int*   apply_mask = (const int*)d_in[2];
    float*       out        = (float*)d_out;

    const int B = in_sizes[1];                 // 256
    const int elems_per_img = in_sizes[0] / B; // 150528
    const int vec_per_img = elems_per_img / 4; // 37632

    const int tile = THREADS * VPT;            // 768
    if ((elems_per_img % 4 == 0) && (vec_per_img % tile == 0) &&
        (vec_per_img % MEAN_CHUNKS_F == 0) && B <= MAX_B) {
        const int blocks_per_img = vec_per_img / tile;   // 49
        const int grid = B * MEAN_CHUNKS_F + B * blocks_per_img;
        fused_kernel<<<grid, THREADS>>>(
            (const float4*)x, sample, apply_mask, (float4*)out,
            blocks_per_img, vec_per_img, B);
    } else {
        dim3 mgrid(B, MEAN_CHUNKS_G);
        mean_kernel<<<mgrid, 256>>>((const float4*)x, sample, apply_mask, vec_per_img);
        dim3 grid((vec_per_img + 255) / 256, B);
        apply_generic<<<grid, 256>>>((const float4*)x, sample, apply_mask,
                                     (float4*)out, vec_per_img);
    }
}

// round 8
// speedup vs baseline: 1.1973x; 1.0006x over previous
#include <cuda_runtime.h>

#define MAX_B        1024
#define MAGS_PER_TF  9
#define THREADS      256
#define VPT          4
#define NWARPS       (THREADS / 32)
#define MEAN_CHUNKS_F 16     // front reducer blocks per image (fused path)

// Persistent device state, zero-initialized at module load. All counters are
// monotonic across graph replays — no reset kernel is ever needed.
__device__ unsigned int          g_mdone[MAX_B];  // reducer-block completions
__device__ unsigned int          g_acnt[MAX_B];   // apply-block epoch counter
__device__ float                 g_sum[MAX_B];    // running sum (reset via atomicExch)
__device__ volatile unsigned int g_flag[MAX_B];   // published epoch number
__device__ volatile float        g_mean[MAX_B];   // published mean

// Generic (non-exact-tiling) fallback path scratch:
#define MEAN_CHUNKS_G 32
__device__ float g_part[MAX_B * MEAN_CHUNKS_G];

// ---------------------------------------------------------------------------
__device__ __forceinline__ float block_reduce(float val)
{
    #pragma unroll
    for (int off = 16; off > 0; off >>= 1)
        val += __shfl_xor_sync(0xFFFFFFFFu, val, off);

    __shared__ float ws[NWARPS];
    const int lane = threadIdx.x & 31;
    const int wid  = threadIdx.x >> 5;
    if (lane == 0) ws[wid] = val;
    __syncthreads();

    float v = 0.0f;
    if (wid == 0) {
        v = (lane < NWARPS) ? ws[lane] : 0.0f;
        #pragma unroll
        for (int off = 4; off > 0; off >>= 1)
            v += __shfl_xor_sync(0xFFFFFFFFu, v, off);
    }
    return v;  // valid in warp 0
}

// Slim streaming apply for N float4s per thread, unpredicated.
template <int N>
__device__ __forceinline__ void stream_apply(const float4* __restrict__ x,
                                             float4* __restrict__ out,
                                             unsigned int base,
                                             float alpha, float beta)
{
    float4 v[N];
    #pragma unroll
    for (int k = 0; k < N; k++)
        v[k] = __ldcs(&x[base + k * THREADS]);

    #pragma unroll
    for (int k = 0; k < N; k++) {
        v[k].x = __saturatef(fmaf(alpha, v[k].x, beta));
        v[k].y = __saturatef(fmaf(alpha, v[k].y, beta));
        v[k].z = __saturatef(fmaf(alpha, v[k].z, beta));
        v[k].w = __saturatef(fmaf(alpha, v[k].w, beta));
        __stcs(&out[base + k * THREADS], v[k]);
    }
}

// ---------------------------------------------------------------------------
// Fused kernel. Grid layout:
//   [0, B*MEAN_CHUNKS_F)        front reducer blocks (contrast images only)
//   [front, front + B*bpi)      apply blocks; per image: (bpi-1) full VPT-4
//                               blocks + 1 exact tail block of tail_vpt (=3)
// Front blocks are scheduled first (in-order CTA placement), so apply blocks
// for contrast images normally find the mean already published.
// ---------------------------------------------------------------------------
__global__ void __launch_bounds__(THREADS)
fused_kernel(const float4* __restrict__ x,
             const int* __restrict__ sample,
             const int* __restrict__ apply_mask,
             float4* __restrict__ out,
             int blocks_per_img,      // includes the tail block
             int tail_vpt,            // float4s/thread in the tail block
             int vec_per_img,
             int B)
{
    const int front = B * MEAN_CHUNKS_F;
    const float inv_n = 1.0f / (float)(vec_per_img * 4);

    if (blockIdx.x < front) {
        // ================= front reducer block =================
        const int b     = blockIdx.x / MEAN_CHUNKS_F;
        const int chunk = blockIdx.x - b * MEAN_CHUNKS_F;

        const int s  = __ldg(&sample[b]);
        const int tf = s / MAGS_PER_TF;
        if (!((tf == 1) && (__ldg(&apply_mask[s]) > 0))) return;  // no read

        const int chunk_vecs = vec_per_img / MEAN_CHUNKS_F;   // exact by launch check
        const unsigned int start = (unsigned int)b * vec_per_img + chunk * chunk_vecs;

        float acc = 0.0f;
        for (int i = threadIdx.x; i < chunk_vecs; i += THREADS) {
            float4 w = __ldg(&x[start + i]);   // cached: apply pass re-reads from L2
            acc += (w.x + w.y) + (w.z + w.w);
        }
        float total = block_reduce(acc);

        if (threadIdx.x == 0) {
            atomicAdd(&g_sum[b], total);
            __threadfence();
            const unsigned int d = atomicAdd(&g_mdone[b], 1u) + 1u;
            if (d % (unsigned int)MEAN_CHUNKS_F == 0u) {
                float sum = atomicExch(&g_sum[b], 0.0f);
                g_mean[b] = sum * inv_n;
                __threadfence();
                g_flag[b] = d / (unsigned int)MEAN_CHUNKS_F;  // publish epoch
            }
        }
        return;
    }

    // ================= apply block =================
    const int abix = blockIdx.x - front;
    const int b    = abix / blocks_per_img;
    const int blk  = abix - b * blocks_per_img;
    const bool is_tail = (blk == blocks_per_img - 1);

    const int s  = __ldg(&sample[b]);
    const int tf = s / MAGS_PER_TF;
    const float mag = (float)(s % MAGS_PER_TF + 1) * 0.1f;
    const bool applied  = (__ldg(&apply_mask[s]) > 0);
    const bool contrast = applied && (tf == 1);

    const unsigned int base = (unsigned int)b * (unsigned int)vec_per_img
                            + (unsigned int)blk * (THREADS * VPT)
                            + threadIdx.x;

    float alpha = 1.0f, beta = 0.0f;

    if (!contrast) {
        if (applied) {
            if (tf == 0)      { beta = mag; }                            // brightness
            else if (tf == 2) { alpha = 1.0f - 2.0f * mag; beta = mag; } // invert
            else              { alpha = 1.0f + mag; }                    // gain
        }
    } else {
        // Mean normally already published by the front blocks.
        __shared__ float s_mean;
        __shared__ int   s_fallback;

        if (threadIdx.x == 0) {
            s_fallback = 0;
            const unsigned int d = atomicAdd(&g_acnt[b], 1u) + 1u;
            const unsigned int bp = (unsigned int)blocks_per_img;
            const unsigned int my_epoch = (d + bp - 1u) / bp;

            int spins = 0;
            while (g_flag[b] < my_epoch) {          // expected: already true
                __nanosleep(40);
                if (++spins > 4000000) { s_fallback = 1; break; }
            }
            if (!s_fallback) {
                __threadfence();                     // acquire
                s_mean = g_mean[b];
            }
        }
        __syncthreads();

        if (s_fallback) {
            // Guaranteed forward progress (never expected): recompute locally.
            const float4* img = x + (size_t)b * vec_per_img;
            float a2 = 0.0f;
            for (int i = threadIdx.x; i < vec_per_img; i += THREADS) {
                float4 w = __ldg(&img[i]);
                a2 += (w.x + w.y) + (w.z + w.w);
            }
            __syncthreads();
            float t2 = block_reduce(a2);
            if (threadIdx.x == 0) s_mean = t2 * inv_n;
            __syncthreads();
        }

        alpha = 1.0f + mag;
        beta  = -s_mean * mag;
    }

    if (!is_tail) {
        stream_apply<VPT>(x, out, base, alpha, beta);
    } else {
        // tail_vpt is 3 for the 37632-vec shape; handle 1..4 generically.
        switch (tail_vpt) {
            case 4: stream_apply<4>(x, out, base, alpha, beta); break;
            case 3: stream_apply<3>(x, out, base, alpha, beta); break;
            case 2: stream_apply<2>(x, out, base, alpha, beta); break;
            default: stream_apply<1>(x, out, base, alpha, beta); break;
        }
    }
}

// ---------------------------------------------------------------------------
// Generic fallback (shapes without exact tiling): two-kernel scheme.
// ---------------------------------------------------------------------------
__global__ void mean_kernel(const float4* __restrict__ x,
                            const int* __restrict__ sample,
                            const int* __restrict__ apply_mask,
                            int vec_per_img)
{
    const int b     = blockIdx.x;
    const int chunk = blockIdx.y;

    const int s  = __ldg(&sample[b]);
    const int tf = s / MAGS_PER_TF;
    if (!((tf == 1) && (__ldg(&apply_mask[s]) > 0))) return;

    const int chunk_vecs = (vec_per_img + MEAN_CHUNKS_G - 1) / MEAN_CHUNKS_G;
    const int start = chunk * chunk_vecs;
    const int end   = min(start + chunk_vecs, vec_per_img);

    const float4* img = x + (size_t)b * vec_per_img;
    float acc = 0.0f;
    for (int i = start + threadIdx.x; i < end; i += blockDim.x) {
        float4 w = __ldg(&img[i]);
        acc += (w.x + w.y) + (w.z + w.w);
    }
    #pragma unroll
    for (int off = 16; off > 0; off >>= 1)
        acc += __shfl_xor_sync(0xFFFFFFFFu, acc, off);

    __shared__ float ws[32];
    const int lane = threadIdx.x & 31;
    const int wid  = threadIdx.x >> 5;
    if (lane == 0) ws[wid] = acc;
    __syncthreads();
    if (wid == 0) {
        const int nwarps = (blockDim.x + 31) >> 5;
        float t = (lane < nwarps) ? ws[lane] : 0.0f;
        #pragma unroll
        for (int off = 16; off > 0; off >>= 1)
            t += __shfl_xor_sync(0xFFFFFFFFu, t, off);
        if (lane == 0) g_part[b * MEAN_CHUNKS_G + chunk] = t;
    }
}

__global__ void apply_generic(const float4* __restrict__ x,
                              const int* __restrict__ sample,
                              const int* __restrict__ apply_mask,
                              float4* __restrict__ out,
                              int vec_per_img)
{
    const int b = blockIdx.y;
    const int i = blockIdx.x * blockDim.x + threadIdx.x;

    const int s  = __ldg(&sample[b]);
    const int tf = s / MAGS_PER_TF;
    const float mag = (float)(s % MAGS_PER_TF + 1) * 0.1f;
    const bool applied = (__ldg(&apply_mask[s]) > 0);

    float alpha = 1.0f, beta = 0.0f;
    if (applied) {
        if (tf == 0) { beta = mag; }
        else if (tf == 1) {
            float sum = 0.0f;
            #pragma unroll
            for (int c = 0; c < MEAN_CHUNKS_G; c++)
                sum += __ldg(&g_part[b * MEAN_CHUNKS_G + c]);
            alpha = 1.0f + mag;
            beta  = -(sum / (float)(vec_per_img * 4)) * mag;
        }
        else if (tf == 2) { alpha = 1.0f - 2.0f * mag; beta = mag; }
        else              { alpha = 1.0f + mag; }
    }

    if (i < vec_per_img) {
        const size_t idx = (size_t)b * vec_per_img + i;
        float4 w = __ldcs(&x[idx]);
        w.x = __saturatef(fmaf(alpha, w.x, beta));
        w.y = __saturatef(fmaf(alpha, w.y, beta));
        w.z = __saturatef(fmaf(alpha, w.z, beta));
        w.w = __saturatef(fmaf(alpha, w.w, beta));
        __stcs(&out[idx], w);
    }
}

// ---------------------------------------------------------------------------
extern "C" void kernel_launch(void* const* d_in, const int* in_sizes, int n_in,
                              void* d_out, int out_size)
{
    const float* x          = (const float*)d_in[0];
    const int*   sample     = (const int*)d_in[1];
    const int*   apply_mask = (const int*)d_in[2];
    float*       out        = (float*)d_out;

    const int B = in_sizes[1];                 // 256
    const int elems_per_img = in_sizes[0] / B; // 150528
    const int vec_per_img = elems_per_img / 4; // 37632

    // Exact tiling: full blocks of THREADS*VPT, plus one tail block of
    // THREADS*tail_vpt, where the remainder must be a multiple of THREADS.
    const int tile = THREADS * VPT;                        // 1024
    const int full = vec_per_img / tile;                   // 36
    const int rem  = vec_per_img - full * tile;            // 768
    const bool exact = (elems_per_img % 4 == 0) && B <= MAX_B &&
                       (vec_per_img % MEAN_CHUNKS_F == 0) &&
                       (rem > 0) && (rem % THREADS == 0) && (rem / THREADS <= VPT);

    if (exact) {
        const int tail_vpt = rem / THREADS;                // 3
        const int blocks_per_img = full + 1;               // 37
        const int grid = B * MEAN_CHUNKS_F + B * blocks_per_img;
        fused_kernel<<<grid, THREADS>>>(
            (const float4*)x, sample, apply_mask, (float4*)out,
            blocks_per_img, tail_vpt, vec_per_img, B);
    } else if ((elems_per_img % 4 == 0) && (rem == 0) &&
               (vec_per_img % MEAN_CHUNKS_F == 0) && B <= MAX_B) {
        // Perfectly divisible: tail block is a full VPT block.
        const int blocks_per_img = full;
        const int grid = B * MEAN_CHUNKS_F + B * blocks_per_img;
        fused_kernel<<<grid, THREADS>>>(
            (const float4*)x, sample, apply_mask, (float4*)out,
            blocks_per_img, VPT, vec_per_img, B);
    } else {
        dim3 mgrid(B, MEAN_CHUNKS_G);
        mean_kernel<<<mgrid, 256>>>((const float4*)x, sample, apply_mask, vec_per_img);
        dim3 grid((vec_per_img + 255) / 256, B);
        apply_generic<<<grid, 256>>>((const float4*)x, sample, apply_mask,
                                     (float4*)out, vec_per_img);
    }
}